// round 11
// baseline (speedup 1.0000x reference)
#include <cuda_runtime.h>
#include <cuda_fp16.h>
#include <cstdint>

// Problem constants (fixed by the dataset)
#define NC   1000      // cells
#define NGOI 500       // genes of interest
#define NGT  5000      // total genes
#define NL   10        // latent dim
#define NK   129       // knots (NBINS+1)
#define RSE  136       // E row stride in halves (272B rows, 16B-aligned)
#define RSB  136       // B row stride in halves
#define NPAIR (NC*NGOI)

#define MAIN_BLOCKS 1184
#define MAIN_THREADS 256
#define CSPLIT 8
#define CPB (NC / CSPLIT)     // 125 cells per block

// ---------------- device scratch (static: no allocation allowed) -------------
__device__ float  g_logits[NC * NGT];                 // 20 MB (lse input only)
__device__ float  g_lse[NC];
__device__ __half g_E[(size_t)NPAIR * RSE];           // 136 MB exp(delta), knots 0..128
__device__ __half g_B[NGOI * RSB];                    // exp(baseline), knots 0..128
__device__ float  g_woP[NGT * 12];                    // [wo(10), ob, 0] per gene
__device__ float  g_latP[NC * 12];                    // [lat(10), 1, 0] per cell
__device__ double g_part[MAIN_BLOCKS];

// ---------------- kernel: overall logits [NC x NGT] (for lse) -----------------
__global__ void k_logits(const float* __restrict__ latent,
                         const float* __restrict__ wo,
                         const float* __restrict__ ob) {
    __shared__ float lat[16 * NL];
    int g  = blockIdx.x * 256 + threadIdx.x;
    int c0 = blockIdx.y * 16;
    int t = threadIdx.x;
    if (t < 16 * NL) {
        int cc = c0 + t / NL;
        lat[t] = (cc < NC) ? latent[cc * NL + t % NL] : 0.f;
    }
    __syncthreads();
    if (g >= NGT) return;
    float w[NL];
#pragma unroll
    for (int l = 0; l < NL; l++) w[l] = wo[g * NL + l];
    float base = ob[g];
    int cmax = NC - c0; if (cmax > 16) cmax = 16;
    for (int c = 0; c < cmax; c++) {
        float a = base;
#pragma unroll
        for (int l = 0; l < NL; l++) a = fmaf(lat[c * NL + l], w[l], a);
        g_logits[(c0 + c) * NGT + g] = a;
    }
}

// ---------------- kernel: per-cell log-sum-exp --------------------------------
__global__ void k_lse() {
    int c = blockIdx.x;
    const float4* row = (const float4*)&g_logits[c * NGT];
    float s = 0.f;
    for (int i = threadIdx.x; i < NGT / 4; i += 512) {
        float4 v = row[i];
        s += __expf(v.x) + __expf(v.y) + __expf(v.z) + __expf(v.w);
    }
    __shared__ float sh[16];
#pragma unroll
    for (int o = 16; o; o >>= 1) s += __shfl_xor_sync(0xffffffffu, s, o);
    if ((threadIdx.x & 31) == 0) sh[threadIdx.x >> 5] = s;
    __syncthreads();
    if (threadIdx.x < 16) {
        s = sh[threadIdx.x];
#pragma unroll
        for (int o = 8; o; o >>= 1) s += __shfl_xor_sync(0xffffu, s, o);
        if (threadIdx.x == 0) g_lse[c] = __logf(s);
    }
}

// ---------------- prep: padded wo rows (ob in slot 10) ------------------------
__global__ void k_woprep(const float* __restrict__ wo, const float* __restrict__ ob) {
    int i = blockIdx.x * 256 + threadIdx.x;
    if (i >= NGT * 12) return;
    int g = i / 12, s = i - g * 12;
    float v = 0.f;
    if (s < NL) v = wo[g * NL + s];
    else if (s == NL) v = ob[g];
    g_woP[i] = v;
}

// ---------------- prep: padded latent rows (1.0 in slot 10) -------------------
__global__ void k_latprep(const float* __restrict__ latent) {
    int i = blockIdx.x * 256 + threadIdx.x;
    if (i >= NC * 12) return;
    int c = i / 12, s = i - c * 12;
    float v = 0.f;
    if (s < NL) v = latent[c * NL + s];
    else if (s == NL) v = 1.f;
    g_latP[i] = v;
}

// ---------------- kernel: baseline exp table ----------------------------------
__global__ void k_bexp(const float* __restrict__ sb, const int* __restrict__ goi) {
    int j = blockIdx.x;
    int gene = goi[j];
    int t = threadIdx.x;
    if (t < NK)
        g_B[j * RSB + t] = __float2half_rn(__expf(sb[(size_t)gene * NK + t]));
}

// ---------------- kernel: exp(delta) fp16 table via HFMA2 ---------------------
// E[c*NGOI+j][k] = exp( sum_l latent[c][l] * hw[goi[j]][l][k] )
// Lane owns knots 4*lane..4*lane+3 as two half2 accumulators; knot 128 via a
// once-per-block fp32 side pass into shared.
__global__ void __launch_bounds__(256, 4) k_delta(const float* __restrict__ latent,
                                                  const float* __restrict__ hw,
                                                  const int*   __restrict__ goi) {
    __shared__ __half2 slat2[CPB * 12];   // splat half2 latent, stride 12 (48B rows)
    __shared__ __half  sE128[CPB];        // exp(delta at knot 128) per cell
    int j = blockIdx.x;
    int gene = goi[j];
    int c0 = blockIdx.y * CPB;
    int tid = threadIdx.x;
    int w = tid >> 5, lane = tid & 31;

    for (int i = tid; i < CPB * NL; i += 256) {
        int cc = i / NL, l = i - cc * NL;
        slat2[cc * 12 + l] = __float2half2_rn(latent[(c0 + cc) * NL + l]);
    }

    int k4 = lane * 4;
    const float* wp = hw + (size_t)gene * NL * NK;
    __half2 W01[NL], W23[NL];
#pragma unroll
    for (int l = 0; l < NL; l++) {
        const float* r = wp + l * NK;
        W01[l] = __floats2half2_rn(r[k4],     r[k4 + 1]);
        W23[l] = __floats2half2_rn(r[k4 + 2], r[k4 + 3]);
    }
    __syncthreads();

    // fp32 side pass: knot-128 delta per cell
    if (tid < CPB) {
        float a = 0.f;
#pragma unroll
        for (int l = 0; l < NL; l++)
            a = fmaf(latent[(c0 + tid) * NL + l], wp[l * NK + 128], a);
        sE128[tid] = __float2half_rn(__expf(a));
    }
    __syncthreads();

    for (int c = w; c < CPB; c += 8) {
        const __half2* sp = &slat2[c * 12];
        // vector-load 10 splat half2 (16B + 16B + 8B)
        uint4 v0 = *(const uint4*)sp;
        uint4 v1 = *(const uint4*)(sp + 4);
        uint2 v2 = *(const uint2*)(sp + 8);
        __half2 lv[NL];
        lv[0] = *(__half2*)&v0.x; lv[1] = *(__half2*)&v0.y;
        lv[2] = *(__half2*)&v0.z; lv[3] = *(__half2*)&v0.w;
        lv[4] = *(__half2*)&v1.x; lv[5] = *(__half2*)&v1.y;
        lv[6] = *(__half2*)&v1.z; lv[7] = *(__half2*)&v1.w;
        lv[8] = *(__half2*)&v2.x; lv[9] = *(__half2*)&v2.y;

        __half2 a01 = __float2half2_rn(0.f);
        __half2 a23 = __float2half2_rn(0.f);
#pragma unroll
        for (int l = 0; l < NL; l++) {
            a01 = __hfma2(lv[l], W01[l], a01);
            a23 = __hfma2(lv[l], W23[l], a23);
        }
        float2 f01 = __half22float2(a01);
        float2 f23 = __half22float2(a23);
        __half2 h01 = __floats2half2_rn(__expf(f01.x), __expf(f01.y));
        __half2 h23 = __floats2half2_rn(__expf(f23.x), __expf(f23.y));
        uint2 st;
        st.x = *(const unsigned*)&h01;
        st.y = *(const unsigned*)&h23;
        size_t rb = (size_t)((c0 + c) * NGOI + j) * RSE;
        *(uint2*)&g_E[rb + k4] = st;
        if (lane == 31) g_E[rb + 128] = sE128[c];
    }
}

// ---------------- kernel: per-cut spline log-prob, 8-lane groups --------------
// Warp handles 4 cuts; 8-lane group reduces one cut's trapezoid norm; sub==0
// lane does interp + inline overall-logit + final logs.
__global__ void __launch_bounds__(MAIN_THREADS) k_main(
        const float* __restrict__ coord,
        const int*   __restrict__ cxg,    // pair index p
        const int*   __restrict__ lcxg,   // cell x total-gene index q
        const int*   __restrict__ gloc,   // local gene index gl
        int ncuts) {
    int lane = threadIdx.x & 31, w = threadIdx.x >> 5;
    int grp = lane >> 3, sub = lane & 7;
    int warpid = blockIdx.x * (MAIN_THREADS >> 5) + w;
    int nwarp = gridDim.x * (MAIN_THREADS >> 5);
    double acc = 0.0;
    const float C = 4.852030263919617f + 8.517193191416238f; // ln(128)+ln(5000)
    const unsigned FULL = 0xffffffffu;

    for (int i4 = warpid * 4; i4 < ncuts; i4 += nwarp * 4) {
        int cut = i4 + grp;
        int cc = (cut < ncuts) ? cut : (ncuts - 1);
        int p  = __ldg(&cxg[cc]);
        int gl = __ldg(&gloc[cc]);

        size_t rb = (size_t)p * RSE;
        const __half* erow = &g_E[rb + sub * 16];
        const __half* brow = &g_B[gl * RSB + sub * 16];
        const uint4 ev0 = *(const uint4*)erow;
        const uint4 ev1 = *(const uint4*)(erow + 8);
        const uint4 bv0 = *(const uint4*)brow;
        const uint4 bv1 = *(const uint4*)(brow + 8);

        __half2 t0 = __hmul2(*(const __half2*)&ev0.x, *(const __half2*)&bv0.x);
        __half2 t1 = __hmul2(*(const __half2*)&ev0.y, *(const __half2*)&bv0.y);
        __half2 t2 = __hmul2(*(const __half2*)&ev0.z, *(const __half2*)&bv0.z);
        __half2 t3 = __hmul2(*(const __half2*)&ev0.w, *(const __half2*)&bv0.w);
        __half2 t4 = __hmul2(*(const __half2*)&ev1.x, *(const __half2*)&bv1.x);
        __half2 t5 = __hmul2(*(const __half2*)&ev1.y, *(const __half2*)&bv1.y);
        __half2 t6 = __hmul2(*(const __half2*)&ev1.z, *(const __half2*)&bv1.z);
        __half2 t7 = __hmul2(*(const __half2*)&ev1.w, *(const __half2*)&bv1.w);

        __half2 t = __hadd2(__hadd2(__hadd2(t0, t1), __hadd2(t2, t3)),
                            __hadd2(__hadd2(t4, t5), __hadd2(t6, t7)));
        float2 tf = __half22float2(t);
        float s = tf.x + tf.y;
        if (sub == 0) s -= 0.5f * __low2float(t0);            // halve bottom endpoint
        if (sub == 7) {
            float u128 = __half2float(g_E[rb + 128]) * __half2float(g_B[gl * RSB + 128]);
            s += 0.5f * u128;                                  // top endpoint (half)
        }
        s += __shfl_xor_sync(FULL, s, 1);
        s += __shfl_xor_sync(FULL, s, 2);
        s += __shfl_xor_sync(FULL, s, 4);

        // ---- interp + inline logit + final math on sub==0 lanes --------------
        if (sub == 0 && cut < ncuts) {
            float x = __ldg(&coord[cc]);
            int   q = __ldg(&lcxg[cc]);
            unsigned uq = (unsigned)q;
            unsigned cell = uq / (unsigned)NGT;
            unsigned g    = uq - cell * (unsigned)NGT;

            float xs = fminf(fmaxf(x, 0.f), 0.999999f) * 128.f;
            int bi = (int)xs; if (bi > 127) bi = 127;
            float alpha = xs - (float)bi;

            float L = __half2float(g_E[rb + bi])     * __half2float(g_B[gl * RSB + bi]);
            float R = __half2float(g_E[rb + bi + 1]) * __half2float(g_B[gl * RSB + bi + 1]);

            // overall logit = latP[cell] . woP[g]  (slot10: 1*ob; slot11: 0)
            const float4* wr = (const float4*)&g_woP[g * 12];
            const float4* lr = (const float4*)&g_latP[cell * 12];
            float4 w0 = __ldg(&wr[0]), w1 = __ldg(&wr[1]), w2 = __ldg(&wr[2]);
            float4 l0 = __ldg(&lr[0]), l1 = __ldg(&lr[1]), l2 = __ldg(&lr[2]);
            float nl = l0.x*w0.x + l0.y*w0.y + l0.z*w0.z + l0.w*w0.w
                     + l1.x*w1.x + l1.y*w1.y + l1.z*w1.z + l1.w*w1.w
                     + l2.x*w2.x + l2.y*w2.y + l2.z*w2.z;
            nl -= g_lse[cell];

            float val = __logf(fmaf(alpha, R - L, L)) - __logf(s) + C + nl;
            acc += (double)val;
        }
    }

    __shared__ double sh[MAIN_THREADS];
    sh[threadIdx.x] = acc;
    __syncthreads();
    for (int o = MAIN_THREADS / 2; o; o >>= 1) {
        if (threadIdx.x < o) sh[threadIdx.x] += sh[threadIdx.x + o];
        __syncthreads();
    }
    if (threadIdx.x == 0) g_part[blockIdx.x] = sh[0];
}

// ---------------- kernel: deterministic final reduce -------------------------
__global__ void k_final(float* __restrict__ out) {
    __shared__ double sh[256];
    double t = 0.0;
    for (int i = threadIdx.x; i < MAIN_BLOCKS; i += 256) t += g_part[i];
    sh[threadIdx.x] = t;
    __syncthreads();
    for (int s = 128; s; s >>= 1) {
        if (threadIdx.x < s) sh[threadIdx.x] += sh[threadIdx.x + s];
        __syncthreads();
    }
    if (threadIdx.x == 0) out[0] = (float)(-sh[0]);   // elbo = -sum(likelihood)
}

// ---------------- launch ------------------------------------------------------
extern "C" void kernel_launch(void* const* d_in, const int* in_sizes, int n_in,
                              void* d_out, int out_size) {
    const float* latent = (const float*)d_in[0];
    const float* coord  = (const float*)d_in[1];
    const int*   goi    = (const int*)  d_in[2];
    const int*   cxg    = (const int*)  d_in[3];   // cut_local_cellxgene_ix
    const int*   lcxg   = (const int*)  d_in[4];   // cut_localcellxgene_ix
    const int*   gloc   = (const int*)  d_in[5];   // cut_local_gene_ix
    const float* hw     = (const float*)d_in[6];   // height_slope_w
    const float* wo     = (const float*)d_in[7];   // overall_slope_w
    const float* ob     = (const float*)d_in[8];   // overall_baseline
    const float* sb     = (const float*)d_in[9];   // spline_baseline
    float* out = (float*)d_out;
    int ncuts = in_sizes[1];

    {
        dim3 grid((NGT + 255) / 256, (NC + 15) / 16);
        k_logits<<<grid, 256>>>(latent, wo, ob);
    }
    k_lse<<<NC, 512>>>();
    k_woprep<<<(NGT * 12 + 255) / 256, 256>>>(wo, ob);
    k_latprep<<<(NC * 12 + 255) / 256, 256>>>(latent);
    k_bexp<<<NGOI, 132>>>(sb, goi);
    {
        dim3 grid(NGOI, CSPLIT);
        k_delta<<<grid, 256>>>(latent, hw, goi);
    }
    k_main<<<MAIN_BLOCKS, MAIN_THREADS>>>(coord, cxg, lcxg, gloc, ncuts);
    k_final<<<1, 256>>>(out);
}